// round 7
// baseline (speedup 1.0000x reference)
#include <cuda_runtime.h>
#include <cuda_bf16.h>
#include <math.h>
#include <stdint.h>

#define BATCH  4
#define LEN    2048
#define DMODEL 1024
#define DIN    2048
#define DSTATE 16
#define DTRANK 64
#define DCONV  4
#define ML     (BATCH * LEN)          // 8192 rows
#define DBCW   (DTRANK + 2 * DSTATE)  // 96

// ---------------- fp32 scratch ----------------
__device__ float g_xz[(size_t)ML * 2 * DIN];   // in-proj output (xc | z)
__device__ float g_xc[(size_t)ML * DIN];       // conv+silu output (fp32 for scan)
__device__ float g_dbc[(size_t)ML * DBCW];     // dt | B | C
__device__ float g_delta[(size_t)ML * DIN];    // softplus(dt @ W_dt + b)

// ---------------- bf16 hi/lo scratch ----------------
__device__ __align__(16) __nv_bfloat16 g_xh[(size_t)ML * DMODEL];
__device__ __align__(16) __nv_bfloat16 g_xl[(size_t)ML * DMODEL];
__device__ __align__(16) __nv_bfloat16 g_Winh[(size_t)2 * DIN * DMODEL];
__device__ __align__(16) __nv_bfloat16 g_Winl[(size_t)2 * DIN * DMODEL];
__device__ __align__(16) __nv_bfloat16 g_xch[(size_t)ML * DIN];
__device__ __align__(16) __nv_bfloat16 g_xcl[(size_t)ML * DIN];
__device__ __align__(16) __nv_bfloat16 g_Wxh[(size_t)DBCW * DIN];
__device__ __align__(16) __nv_bfloat16 g_Wxl[(size_t)DBCW * DIN];
__device__ __align__(16) __nv_bfloat16 g_dth[(size_t)ML * DTRANK];
__device__ __align__(16) __nv_bfloat16 g_dtl[(size_t)ML * DTRANK];
__device__ __align__(16) __nv_bfloat16 g_Wdth[(size_t)DIN * DTRANK];
__device__ __align__(16) __nv_bfloat16 g_Wdtl[(size_t)DIN * DTRANK];
__device__ __align__(16) __nv_bfloat16 g_yh[(size_t)ML * DIN];
__device__ __align__(16) __nv_bfloat16 g_yl[(size_t)ML * DIN];
__device__ __align__(16) __nv_bfloat16 g_Wouth[(size_t)DMODEL * DIN];
__device__ __align__(16) __nv_bfloat16 g_Woutl[(size_t)DMODEL * DIN];

// ---------------- PTX helpers (base sm_103-legal only) ----------------
__device__ __forceinline__ uint32_t s2u(const void* p) {
    uint32_t a;
    asm("{ .reg .u64 t; cvta.to.shared.u64 t, %1; cvt.u32.u64 %0, t; }" : "=r"(a) : "l"(p));
    return a;
}
__device__ __forceinline__ void cpasync16(uint32_t dst, const void* src, int sz) {
    asm volatile("cp.async.cg.shared.global [%0], [%1], 16, %2;"
                 :: "r"(dst), "l"(src), "r"(sz) : "memory");
}
__device__ __forceinline__ void ldsm4(uint32_t* r, uint32_t addr) {
    asm volatile("ldmatrix.sync.aligned.m8n8.x4.shared.b16 {%0,%1,%2,%3}, [%4];"
                 : "=r"(r[0]), "=r"(r[1]), "=r"(r[2]), "=r"(r[3]) : "r"(addr));
}
__device__ __forceinline__ void mma16816(float* d, const uint32_t* a,
                                         uint32_t b0, uint32_t b1) {
    asm volatile(
        "mma.sync.aligned.m16n8k16.row.col.f32.bf16.bf16.f32 "
        "{%0,%1,%2,%3}, {%4,%5,%6,%7}, {%8,%9}, {%0,%1,%2,%3};"
        : "+f"(d[0]), "+f"(d[1]), "+f"(d[2]), "+f"(d[3])
        : "r"(a[0]), "r"(a[1]), "r"(a[2]), "r"(a[3]), "r"(b0), "r"(b1));
}
#define SWZ(o) ((o) ^ (((o) >> 3) & 0x70))

// ============================================================================
// split-bf16 GEMM (mma.sync):  C[m,n] = sum_k A[m,k]*B[n,k]
//   3 K-segments: Ah*Bh + Al*Bh + Ah*Bl.  CTA tile 128 x BN, BK=64,
//   3-stage cp.async pipeline, ONE __syncthreads per chunk, SW128 swizzle,
//   8 warps (2x4) at 64 x (BN/4) warp tiles.
//   M % 128 == 0, K % 64 == 0; B rows >= N zero-filled; stores guarded n<N.
//   EPI: 0 = plain store, 1 = softplus(acc + bias[n]).
// ============================================================================
template <int BN, int EPI>
__global__ __launch_bounds__(256) void gemm_hl(
    const __nv_bfloat16* __restrict__ Ah, const __nv_bfloat16* __restrict__ Al,
    const __nv_bfloat16* __restrict__ Bh, const __nv_bfloat16* __restrict__ Bl,
    float* __restrict__ C, int N, int K, const float* __restrict__ bias)
{
    constexpr int WN = BN / 4;        // warp n-extent (64 or 32)
    constexpr int NJ = WN / 8;        // n8 tiles per warp (8 or 4)
    constexpr int NB = WN / 16;       // 16-row ldsm groups per warp (4 or 2)
    constexpr int ASTG = 128 * 128;   // A stage bytes (128 rows x 128B)
    constexpr int BSTG = BN * 128;    // B stage bytes
    constexpr int BQ = BN / 32;       // B uint4 loads per thread

    extern __shared__ char dsm[];
    char* base = (char*)((((uintptr_t)dsm) + 1023) & ~(uintptr_t)1023);
    uint32_t sA[3], sB[3];
#pragma unroll
    for (int s = 0; s < 3; s++) {
        sA[s] = s2u(base) + s * (ASTG + BSTG);
        sB[s] = sA[s] + ASTG;
    }

    const int tid = threadIdx.x, lane = tid & 31, wid = tid >> 5;
    const int wm = (wid & 1) * 64, wn = (wid >> 1) * WN;
    const int m0 = blockIdx.y * 128, n0 = blockIdx.x * BN;
    const int kcs = K >> 6, T = 3 * kcs;

    float acc[4][NJ][4];
#pragma unroll
    for (int i = 0; i < 4; i++)
#pragma unroll
        for (int j = 0; j < NJ; j++)
#pragma unroll
            for (int r = 0; r < 4; r++) acc[i][j][r] = 0.f;

    auto loadChunk = [&](int c, int buf) {
        const int seg = c / kcs, kc = c - seg * kcs, koff = kc * 64;
        const __nv_bfloat16* Ap = (seg == 1) ? Al : Ah;
        const __nv_bfloat16* Bp = (seg == 2) ? Bl : Bh;
#pragma unroll
        for (int q = 0; q < 4; q++) {                  // A: 128 x 64
            int idx = tid + q * 256, r = idx >> 3, c8 = idx & 7;
            uint32_t o = (uint32_t)(r * 128 + c8 * 16);
            cpasync16(sA[buf] + SWZ(o), Ap + (size_t)(m0 + r) * K + koff + c8 * 8, 16);
        }
#pragma unroll
        for (int q = 0; q < BQ; q++) {                 // B: BN x 64 (zfill rows >= N)
            int idx = tid + q * 256, r = idx >> 3, c8 = idx & 7;
            int nr = n0 + r;
            int ok = (nr < N) ? 16 : 0;
            uint32_t o = (uint32_t)(r * 128 + c8 * 16);
            cpasync16(sB[buf] + SWZ(o),
                      Bp + (size_t)((nr < N) ? nr : 0) * K + koff + c8 * 8, ok);
        }
        asm volatile("cp.async.commit_group;" ::: "memory");
    };

    loadChunk(0, 0);
    loadChunk(1, 1);

    for (int c = 0; c < T; c++) {
        const int buf = c % 3;
        asm volatile("cp.async.wait_group 1;" ::: "memory");  // chunk c arrived
        __syncthreads();                                       // all done with buf (c-1)%3 compute
        if (c + 2 < T) loadChunk(c + 2, (c + 2) % 3);

        const int rsel = lane & 15;
#pragma unroll
        for (int kb = 0; kb < 64; kb += 16) {
            const int kk = kb + ((lane & 16) >> 1);
            uint32_t af[4][4], bfr[NB][4];
#pragma unroll
            for (int mi = 0; mi < 4; mi++) {
                uint32_t o = (uint32_t)((wm + mi * 16 + rsel) * 128 + kk * 2);
                ldsm4(af[mi], sA[buf] + SWZ(o));
            }
#pragma unroll
            for (int nb = 0; nb < NB; nb++) {
                uint32_t o = (uint32_t)((wn + nb * 16 + rsel) * 128 + kk * 2);
                ldsm4(bfr[nb], sB[buf] + SWZ(o));
            }
#pragma unroll
            for (int mi = 0; mi < 4; mi++)
#pragma unroll
                for (int nj = 0; nj < NJ; nj++)
                    mma16816(acc[mi][nj], af[mi],
                             bfr[nj >> 1][nj & 1], bfr[nj >> 1][(nj & 1) + 2]);
        }
    }

    // epilogue
#pragma unroll
    for (int mi = 0; mi < 4; mi++)
#pragma unroll
        for (int h = 0; h < 2; h++) {
            int m = m0 + wm + mi * 16 + (lane >> 2) + h * 8;
#pragma unroll
            for (int nj = 0; nj < NJ; nj++) {
                int n = n0 + wn + nj * 8 + (lane & 3) * 2;
                if (n < N) {
                    float v0 = acc[mi][nj][h * 2 + 0];
                    float v1 = acc[mi][nj][h * 2 + 1];
                    if (EPI == 1) {
                        v0 += bias[n];
                        v1 += bias[n + 1];
                        v0 = fmaxf(v0, 0.f) + log1pf(expf(-fabsf(v0)));
                        v1 = fmaxf(v1, 0.f) + log1pf(expf(-fabsf(v1)));
                    }
                    *(float2*)(C + (size_t)m * N + n) = make_float2(v0, v1);
                }
            }
        }
}

// ---------------- fp32 -> (hi, lo) bf16 split, contiguous ----------------
__global__ __launch_bounds__(256) void split_hl(
    const float* __restrict__ src, __nv_bfloat16* __restrict__ h,
    __nv_bfloat16* __restrict__ l, int n4)
{
    int i = blockIdx.x * 256 + threadIdx.x;
    if (i >= n4) return;
    float4 v = ((const float4*)src)[i];
    __nv_bfloat16 h0 = __float2bfloat16(v.x), h1 = __float2bfloat16(v.y);
    __nv_bfloat16 h2 = __float2bfloat16(v.z), h3 = __float2bfloat16(v.w);
    __nv_bfloat16 l0 = __float2bfloat16(v.x - __bfloat162float(h0));
    __nv_bfloat16 l1 = __float2bfloat16(v.y - __bfloat162float(h1));
    __nv_bfloat16 l2 = __float2bfloat16(v.z - __bfloat162float(h2));
    __nv_bfloat16 l3 = __float2bfloat16(v.w - __bfloat162float(h3));
    ((__nv_bfloat162*)h)[i * 2 + 0] = __nv_bfloat162(h0, h1);
    ((__nv_bfloat162*)h)[i * 2 + 1] = __nv_bfloat162(h2, h3);
    ((__nv_bfloat162*)l)[i * 2 + 0] = __nv_bfloat162(l0, l1);
    ((__nv_bfloat162*)l)[i * 2 + 1] = __nv_bfloat162(l2, l3);
}

// ---------------- dt slice (cols 0..63 of g_dbc) -> hi/lo ----------------
__global__ __launch_bounds__(256) void split_dt_kernel()
{
    int i = blockIdx.x * 256 + threadIdx.x;          // over ML*16, 4 elems each
    if (i >= ML * 16) return;
    int r = i >> 4, c = (i & 15) * 4;
    float4 v = *(const float4*)&g_dbc[(size_t)r * DBCW + c];
    __nv_bfloat16 h0 = __float2bfloat16(v.x), h1 = __float2bfloat16(v.y);
    __nv_bfloat16 h2 = __float2bfloat16(v.z), h3 = __float2bfloat16(v.w);
    __nv_bfloat16 l0 = __float2bfloat16(v.x - __bfloat162float(h0));
    __nv_bfloat16 l1 = __float2bfloat16(v.y - __bfloat162float(h1));
    __nv_bfloat16 l2 = __float2bfloat16(v.z - __bfloat162float(h2));
    __nv_bfloat16 l3 = __float2bfloat16(v.w - __bfloat162float(h3));
    size_t o = (size_t)r * DTRANK + c;
    ((__nv_bfloat162*)(g_dth + o))[0] = __nv_bfloat162(h0, h1);
    ((__nv_bfloat162*)(g_dth + o))[1] = __nv_bfloat162(h2, h3);
    ((__nv_bfloat162*)(g_dtl + o))[0] = __nv_bfloat162(l0, l1);
    ((__nv_bfloat162*)(g_dtl + o))[1] = __nv_bfloat162(l2, l3);
}

// ---------------- causal depthwise conv (k=4) + bias + SiLU + bf16 split ----
__global__ __launch_bounds__(256) void conv_silu_kernel(
    const float* __restrict__ w, const float* __restrict__ bias)
{
    int idx = blockIdx.x * blockDim.x + threadIdx.x;
    if (idx >= ML * DIN) return;
    int d = idx & (DIN - 1);
    int l = (idx >> 11) & (LEN - 1);
    int b = idx >> 22;

    float acc = bias[d];
    const float* wd = w + d * DCONV;
#pragma unroll
    for (int j = 0; j < DCONV; j++) {
        int ll = l - (DCONV - 1) + j;
        if (ll >= 0)
            acc = fmaf(wd[j], g_xz[((size_t)(b * LEN + ll)) * (2 * DIN) + d], acc);
    }
    float s = acc / (1.f + __expf(-acc));
    g_xc[idx] = s;
    __nv_bfloat16 hi = __float2bfloat16(s);
    g_xch[idx] = hi;
    g_xcl[idx] = __float2bfloat16(s - __bfloat162float(hi));
}

// ---------------- selective scan + D skip + SiLU(z) gate + bf16 split ------
// grid (DIN/64, BATCH), 256 threads: 64 channels x 4 state-quads.
__global__ __launch_bounds__(256) void scan_kernel(
    const float* __restrict__ A_raw, const float* __restrict__ Dp)
{
    const int b = blockIdx.y;
    const int d = blockIdx.x * 64 + (threadIdx.x >> 2);
    const int q = threadIdx.x & 3;
    const int n0 = q * 4;

    float A2[4];
#pragma unroll
    for (int n = 0; n < 4; n++)
        A2[n] = -expf(A_raw[(size_t)(n0 + n) * DIN + d]) * 1.4426950408889634f;
    const float Dd = Dp[d];

    float h[4] = {0.f, 0.f, 0.f, 0.f};
    const float* dbcb = g_dbc + (size_t)b * LEN * DBCW + DTRANK;
    const size_t base = (size_t)b * LEN;

    // prefetch l = 0
    size_t r0 = base * DIN + d;
    float dlt = g_delta[r0];
    float xv  = g_xc[r0];
    float zv  = g_xz[base * (2 * DIN) + DIN + d];

    for (int l = 0; l < LEN; l++) {
        float c_dlt = dlt, c_x = xv, c_z = zv;
        int ln = (l + 1 < LEN) ? l + 1 : l;            // prefetch next
        size_t rn = (base + ln) * DIN + d;
        dlt = g_delta[rn];
        xv  = g_xc[rn];
        zv  = g_xz[(base + ln) * (2 * DIN) + DIN + d];

        const float* bc = dbcb + (size_t)l * DBCW;
        float dx = c_dlt * c_x;
        float yv = 0.f;
#pragma unroll
        for (int n = 0; n < 4; n++) {
            float Bn = bc[n0 + n];
            float Cn = bc[DSTATE + n0 + n];
            float dA = exp2f(c_dlt * A2[n]);
            h[n] = fmaf(dA, h[n], Bn * dx);
            yv = fmaf(Cn, h[n], yv);
        }
        yv += __shfl_xor_sync(0xFFFFFFFFu, yv, 1);
        yv += __shfl_xor_sync(0xFFFFFFFFu, yv, 2);
        if (q == 0) {
            float y = fmaf(Dd, c_x, yv);
            float gate = c_z / (1.f + __expf(-c_z));
            float o = y * gate;
            size_t oi = (base + l) * DIN + d;
            __nv_bfloat16 hi = __float2bfloat16(o);
            g_yh[oi] = hi;
            g_yl[oi] = __float2bfloat16(o - __bfloat162float(hi));
        }
    }
}

// ---------------- launch ---------------------------------------------------
extern "C" void kernel_launch(void* const* d_in, const int* in_sizes, int n_in,
                              void* d_out, int out_size)
{
    const float* x      = (const float*)d_in[0];
    const float* W_in   = (const float*)d_in[1];
    const float* conv_w = (const float*)d_in[2];
    const float* conv_b = (const float*)d_in[3];
    const float* W_x    = (const float*)d_in[4];
    const float* W_dt   = (const float*)d_in[5];
    const float* b_dt   = (const float*)d_in[6];
    const float* A_raw  = (const float*)d_in[7];
    const float* Dp     = (const float*)d_in[8];
    const float* W_out  = (const float*)d_in[9];
    float* out = (float*)d_out;

    float *p_xz, *p_dbc, *p_delta;
    __nv_bfloat16 *p_xh, *p_xl, *p_Winh, *p_Winl, *p_xch, *p_xcl, *p_Wxh, *p_Wxl;
    __nv_bfloat16 *p_dth, *p_dtl, *p_Wdth, *p_Wdtl, *p_yh, *p_yl, *p_Wouth, *p_Woutl;
    cudaGetSymbolAddress((void**)&p_xz,    g_xz);
    cudaGetSymbolAddress((void**)&p_dbc,   g_dbc);
    cudaGetSymbolAddress((void**)&p_delta, g_delta);
    cudaGetSymbolAddress((void**)&p_xh,    g_xh);
    cudaGetSymbolAddress((void**)&p_xl,    g_xl);
    cudaGetSymbolAddress((void**)&p_Winh,  g_Winh);
    cudaGetSymbolAddress((void**)&p_Winl,  g_Winl);
    cudaGetSymbolAddress((void**)&p_xch,   g_xch);
    cudaGetSymbolAddress((void**)&p_xcl,   g_xcl);
    cudaGetSymbolAddress((void**)&p_Wxh,   g_Wxh);
    cudaGetSymbolAddress((void**)&p_Wxl,   g_Wxl);
    cudaGetSymbolAddress((void**)&p_dth,   g_dth);
    cudaGetSymbolAddress((void**)&p_dtl,   g_dtl);
    cudaGetSymbolAddress((void**)&p_Wdth,  g_Wdth);
    cudaGetSymbolAddress((void**)&p_Wdtl,  g_Wdtl);
    cudaGetSymbolAddress((void**)&p_yh,    g_yh);
    cudaGetSymbolAddress((void**)&p_yl,    g_yl);
    cudaGetSymbolAddress((void**)&p_Wouth, g_Wouth);
    cudaGetSymbolAddress((void**)&p_Woutl, g_Woutl);

    const int SM256 = 1024 + 3 * (128 * 128 + 256 * 128);  // 148480
    const int SM128 = 1024 + 3 * (128 * 128 + 128 * 128);  //  99328
    cudaFuncSetAttribute(gemm_hl<256, 0>, cudaFuncAttributeMaxDynamicSharedMemorySize, SM256);
    cudaFuncSetAttribute(gemm_hl<256, 1>, cudaFuncAttributeMaxDynamicSharedMemorySize, SM256);
    cudaFuncSetAttribute(gemm_hl<128, 0>, cudaFuncAttributeMaxDynamicSharedMemorySize, SM128);

    // 1. splits for in-proj
    split_hl<<<(ML * DMODEL / 4 + 255) / 256, 256>>>(x, p_xh, p_xl, ML * DMODEL / 4);
    split_hl<<<(2 * DIN * DMODEL / 4 + 255) / 256, 256>>>(W_in, p_Winh, p_Winl,
                                                          2 * DIN * DMODEL / 4);
    // 2. in-proj GEMM: (8192 x 4096) K=1024
    gemm_hl<256, 0><<<dim3(4096 / 256, ML / 128), 256, SM256>>>(
        p_xh, p_xl, p_Winh, p_Winl, p_xz, 4096, DMODEL, nullptr);
    // 3. conv + SiLU (+ bf16 split of xc)
    conv_silu_kernel<<<(ML * DIN + 255) / 256, 256>>>(conv_w, conv_b);
    // 4. x-proj GEMM: (8192 x 96) K=2048
    split_hl<<<(DBCW * DIN / 4 + 255) / 256, 256>>>(W_x, p_Wxh, p_Wxl, DBCW * DIN / 4);
    gemm_hl<128, 0><<<dim3(1, ML / 128), 256, SM128>>>(
        p_xch, p_xcl, p_Wxh, p_Wxl, p_dbc, DBCW, DIN, nullptr);
    // 5. delta GEMM with fused bias+softplus: (8192 x 2048) K=64
    split_dt_kernel<<<(ML * 16 + 255) / 256, 256>>>();
    split_hl<<<(DIN * DTRANK / 4 + 255) / 256, 256>>>(W_dt, p_Wdth, p_Wdtl,
                                                      DIN * DTRANK / 4);
    gemm_hl<256, 1><<<dim3(DIN / 256, ML / 128), 256, SM256>>>(
        p_dth, p_dtl, p_Wdth, p_Wdtl, p_delta, DIN, DTRANK, b_dt);
    // 6. selective scan (+D skip, gate, bf16 split of y)
    scan_kernel<<<dim3(DIN / 64, BATCH), 256>>>(A_raw, Dp);
    // 7. out-proj GEMM: (8192 x 1024) K=2048
    split_hl<<<(DMODEL * DIN / 4 + 255) / 256, 256>>>(W_out, p_Wouth, p_Woutl,
                                                      DMODEL * DIN / 4);
    gemm_hl<256, 0><<<dim3(DMODEL / 256, ML / 128), 256, SM256>>>(
        p_yh, p_yl, p_Wouth, p_Woutl, out, DMODEL, DIN, nullptr);
}

// round 8
// speedup vs baseline: 1.0111x; 1.0111x over previous
#include <cuda_runtime.h>
#include <cuda_bf16.h>
#include <math.h>
#include <stdint.h>

#define BATCH  4
#define LEN    2048
#define DMODEL 1024
#define DIN    2048
#define DSTATE 16
#define DTRANK 64
#define DCONV  4
#define ML     (BATCH * LEN)          // 8192 rows
#define DBCW   (DTRANK + 2 * DSTATE)  // 96

// ---------------- fp32 scratch ----------------
__device__ float g_xz[(size_t)ML * 2 * DIN];   // in-proj output (xc | z)
__device__ float g_xc[(size_t)ML * DIN];       // conv+silu output (fp32 for scan)
__device__ float g_dbc[(size_t)ML * DBCW];     // dt | B | C
__device__ float g_delta[(size_t)ML * DIN];    // softplus(dt @ W_dt + b)

// ---------------- bf16 hi/lo scratch ----------------
__device__ __align__(16) __nv_bfloat16 g_xh[(size_t)ML * DMODEL];
__device__ __align__(16) __nv_bfloat16 g_xl[(size_t)ML * DMODEL];
__device__ __align__(16) __nv_bfloat16 g_Winh[(size_t)2 * DIN * DMODEL];
__device__ __align__(16) __nv_bfloat16 g_Winl[(size_t)2 * DIN * DMODEL];
__device__ __align__(16) __nv_bfloat16 g_xch[(size_t)ML * DIN];
__device__ __align__(16) __nv_bfloat16 g_xcl[(size_t)ML * DIN];
__device__ __align__(16) __nv_bfloat16 g_Wxh[(size_t)DBCW * DIN];
__device__ __align__(16) __nv_bfloat16 g_Wxl[(size_t)DBCW * DIN];
__device__ __align__(16) __nv_bfloat16 g_dth[(size_t)ML * DTRANK];
__device__ __align__(16) __nv_bfloat16 g_dtl[(size_t)ML * DTRANK];
__device__ __align__(16) __nv_bfloat16 g_Wdth[(size_t)DIN * DTRANK];
__device__ __align__(16) __nv_bfloat16 g_Wdtl[(size_t)DIN * DTRANK];
__device__ __align__(16) __nv_bfloat16 g_yh[(size_t)ML * DIN];
__device__ __align__(16) __nv_bfloat16 g_yl[(size_t)ML * DIN];
__device__ __align__(16) __nv_bfloat16 g_Wouth[(size_t)DMODEL * DIN];
__device__ __align__(16) __nv_bfloat16 g_Woutl[(size_t)DMODEL * DIN];

// ---------------- PTX helpers (base sm_103-legal only) ----------------
__device__ __forceinline__ uint32_t s2u(const void* p) {
    uint32_t a;
    asm("{ .reg .u64 t; cvta.to.shared.u64 t, %1; cvt.u32.u64 %0, t; }" : "=r"(a) : "l"(p));
    return a;
}
__device__ __forceinline__ void cpasync16(uint32_t dst, const void* src, int sz) {
    asm volatile("cp.async.cg.shared.global [%0], [%1], 16, %2;"
                 :: "r"(dst), "l"(src), "r"(sz) : "memory");
}
__device__ __forceinline__ void ldsm4(uint32_t* r, uint32_t addr) {
    asm volatile("ldmatrix.sync.aligned.m8n8.x4.shared.b16 {%0,%1,%2,%3}, [%4];"
                 : "=r"(r[0]), "=r"(r[1]), "=r"(r[2]), "=r"(r[3]) : "r"(addr));
}
__device__ __forceinline__ void mma16816(float* d, const uint32_t* a,
                                         uint32_t b0, uint32_t b1) {
    asm volatile(
        "mma.sync.aligned.m16n8k16.row.col.f32.bf16.bf16.f32 "
        "{%0,%1,%2,%3}, {%4,%5,%6,%7}, {%8,%9}, {%0,%1,%2,%3};"
        : "+f"(d[0]), "+f"(d[1]), "+f"(d[2]), "+f"(d[3])
        : "r"(a[0]), "r"(a[1]), "r"(a[2]), "r"(a[3]), "r"(b0), "r"(b1));
}
#define SWZ(o) ((o) ^ (((o) >> 3) & 0x70))

// ============================================================================
// split-bf16 GEMM (mma.sync):  C[m,n] = sum_k A[m,k]*B[n,k]
//   3 K-segments: Ah*Bh + Al*Bh + Ah*Bl.  CTA tile 128x128, BK=64,
//   3-stage cp.async pipeline, ONE __syncthreads per chunk, SW128 swizzle,
//   8 warps at 64x32 warp tiles, 2 CTAs/SM (regs capped via launch_bounds).
//   M % 128 == 0, K % 64 == 0; B rows >= N zero-filled; stores guarded n<N.
//   EPI: 0 = plain store, 1 = softplus(acc + bias[n]),
//        2 = plain store + (n<64) write bf16 hi/lo into g_dth/g_dtl (dt split).
// ============================================================================
template <int EPI>
__global__ __launch_bounds__(256, 2) void gemm_hl(
    const __nv_bfloat16* __restrict__ Ah, const __nv_bfloat16* __restrict__ Al,
    const __nv_bfloat16* __restrict__ Bh, const __nv_bfloat16* __restrict__ Bl,
    float* __restrict__ C, int N, int K, const float* __restrict__ bias)
{
    extern __shared__ char dsm[];
    char* base = (char*)((((uintptr_t)dsm) + 1023) & ~(uintptr_t)1023);
    uint32_t sA[3], sB[3];
#pragma unroll
    for (int s = 0; s < 3; s++) {
        sA[s] = s2u(base) + s * 32768;
        sB[s] = sA[s] + 16384;
    }

    const int tid = threadIdx.x, lane = tid & 31, wid = tid >> 5;
    const int wm = (wid >> 2) * 64, wn = (wid & 3) * 32;
    const int m0 = blockIdx.y * 128, n0 = blockIdx.x * 128;
    const int kcs = K >> 6, T = 3 * kcs;

    float acc[4][4][4];
#pragma unroll
    for (int i = 0; i < 4; i++)
#pragma unroll
        for (int j = 0; j < 4; j++)
#pragma unroll
            for (int r = 0; r < 4; r++) acc[i][j][r] = 0.f;

    auto loadChunk = [&](int c, int buf) {
        const int seg = c / kcs, kc = c - seg * kcs, koff = kc * 64;
        const __nv_bfloat16* Ap = (seg == 1) ? Al : Ah;
        const __nv_bfloat16* Bp = (seg == 2) ? Bl : Bh;
#pragma unroll
        for (int q = 0; q < 4; q++) {                  // A: 128 x 64
            int idx = tid + q * 256, r = idx >> 3, c8 = idx & 7;
            uint32_t o = (uint32_t)(r * 128 + c8 * 16);
            cpasync16(sA[buf] + SWZ(o), Ap + (size_t)(m0 + r) * K + koff + c8 * 8, 16);
        }
#pragma unroll
        for (int q = 0; q < 4; q++) {                  // B: 128 x 64 (zfill rows >= N)
            int idx = tid + q * 256, r = idx >> 3, c8 = idx & 7;
            int nr = n0 + r;
            int ok = (nr < N) ? 16 : 0;
            uint32_t o = (uint32_t)(r * 128 + c8 * 16);
            cpasync16(sB[buf] + SWZ(o),
                      Bp + (size_t)((nr < N) ? nr : 0) * K + koff + c8 * 8, ok);
        }
        asm volatile("cp.async.commit_group;" ::: "memory");
    };

    loadChunk(0, 0);
    loadChunk(1, 1);

    for (int c = 0; c < T; c++) {
        const int buf = c % 3;
        asm volatile("cp.async.wait_group 1;" ::: "memory");  // chunk c landed
        __syncthreads();                                       // compute(c-1) fully done
        if (c + 2 < T) loadChunk(c + 2, (c + 2) % 3);          // overwrites buf (c-1)%3

        const int rsel = lane & 15;
#pragma unroll
        for (int kb = 0; kb < 64; kb += 16) {
            const int kk = kb + ((lane & 16) >> 1);
            uint32_t af[4][4], bfr[2][4];
#pragma unroll
            for (int mi = 0; mi < 4; mi++) {
                uint32_t o = (uint32_t)((wm + mi * 16 + rsel) * 128 + kk * 2);
                ldsm4(af[mi], sA[buf] + SWZ(o));
            }
#pragma unroll
            for (int nb = 0; nb < 2; nb++) {
                uint32_t o = (uint32_t)((wn + nb * 16 + rsel) * 128 + kk * 2);
                ldsm4(bfr[nb], sB[buf] + SWZ(o));
            }
#pragma unroll
            for (int mi = 0; mi < 4; mi++)
#pragma unroll
                for (int nj = 0; nj < 4; nj++)
                    mma16816(acc[mi][nj], af[mi],
                             bfr[nj >> 1][nj & 1], bfr[nj >> 1][(nj & 1) + 2]);
        }
    }

    // epilogue
#pragma unroll
    for (int mi = 0; mi < 4; mi++)
#pragma unroll
        for (int h = 0; h < 2; h++) {
            int m = m0 + wm + mi * 16 + (lane >> 2) + h * 8;
#pragma unroll
            for (int nj = 0; nj < 4; nj++) {
                int n = n0 + wn + nj * 8 + (lane & 3) * 2;
                if (n < N) {
                    float v0 = acc[mi][nj][h * 2 + 0];
                    float v1 = acc[mi][nj][h * 2 + 1];
                    if (EPI == 1) {
                        v0 += bias[n];
                        v1 += bias[n + 1];
                        v0 = fmaxf(v0, 0.f) + log1pf(expf(-fabsf(v0)));
                        v1 = fmaxf(v1, 0.f) + log1pf(expf(-fabsf(v1)));
                    }
                    *(float2*)(C + (size_t)m * N + n) = make_float2(v0, v1);
                    if (EPI == 2 && n < DTRANK) {      // fused dt hi/lo split
                        __nv_bfloat16 h0 = __float2bfloat16(v0);
                        __nv_bfloat16 h1 = __float2bfloat16(v1);
                        __nv_bfloat16 l0 = __float2bfloat16(v0 - __bfloat162float(h0));
                        __nv_bfloat16 l1 = __float2bfloat16(v1 - __bfloat162float(h1));
                        size_t o = (size_t)m * DTRANK + n;
                        *(__nv_bfloat162*)(g_dth + o) = __nv_bfloat162(h0, h1);
                        *(__nv_bfloat162*)(g_dtl + o) = __nv_bfloat162(l0, l1);
                    }
                }
            }
        }
}

// ---------------- fp32 -> (hi, lo) bf16 split, contiguous ----------------
__global__ __launch_bounds__(256) void split_hl(
    const float* __restrict__ src, __nv_bfloat16* __restrict__ h,
    __nv_bfloat16* __restrict__ l, int n4)
{
    int i = blockIdx.x * 256 + threadIdx.x;
    if (i >= n4) return;
    float4 v = ((const float4*)src)[i];
    __nv_bfloat16 h0 = __float2bfloat16(v.x), h1 = __float2bfloat16(v.y);
    __nv_bfloat16 h2 = __float2bfloat16(v.z), h3 = __float2bfloat16(v.w);
    __nv_bfloat16 l0 = __float2bfloat16(v.x - __bfloat162float(h0));
    __nv_bfloat16 l1 = __float2bfloat16(v.y - __bfloat162float(h1));
    __nv_bfloat16 l2 = __float2bfloat16(v.z - __bfloat162float(h2));
    __nv_bfloat16 l3 = __float2bfloat16(v.w - __bfloat162float(h3));
    ((__nv_bfloat162*)h)[i * 2 + 0] = __nv_bfloat162(h0, h1);
    ((__nv_bfloat162*)h)[i * 2 + 1] = __nv_bfloat162(h2, h3);
    ((__nv_bfloat162*)l)[i * 2 + 0] = __nv_bfloat162(l0, l1);
    ((__nv_bfloat162*)l)[i * 2 + 1] = __nv_bfloat162(l2, l3);
}

// ---------------- causal depthwise conv (k=4) + bias + SiLU + bf16 split ----
__global__ __launch_bounds__(256) void conv_silu_kernel(
    const float* __restrict__ w, const float* __restrict__ bias)
{
    int idx = blockIdx.x * blockDim.x + threadIdx.x;
    if (idx >= ML * DIN) return;
    int d = idx & (DIN - 1);
    int l = (idx >> 11) & (LEN - 1);
    int b = idx >> 22;

    float acc = bias[d];
    const float* wd = w + d * DCONV;
#pragma unroll
    for (int j = 0; j < DCONV; j++) {
        int ll = l - (DCONV - 1) + j;
        if (ll >= 0)
            acc = fmaf(wd[j], g_xz[((size_t)(b * LEN + ll)) * (2 * DIN) + d], acc);
    }
    float s = acc / (1.f + __expf(-acc));
    g_xc[idx] = s;
    __nv_bfloat16 hi = __float2bfloat16(s);
    g_xch[idx] = hi;
    g_xcl[idx] = __float2bfloat16(s - __bfloat162float(hi));
}

// ---------------- selective scan + D skip + SiLU(z) gate + bf16 split ------
// grid (DIN/64, BATCH), 256 threads: 64 channels x 4 state-quads.
__global__ __launch_bounds__(256) void scan_kernel(
    const float* __restrict__ A_raw, const float* __restrict__ Dp)
{
    const int b = blockIdx.y;
    const int d = blockIdx.x * 64 + (threadIdx.x >> 2);
    const int q = threadIdx.x & 3;
    const int n0 = q * 4;

    float A2[4];
#pragma unroll
    for (int n = 0; n < 4; n++)
        A2[n] = -expf(A_raw[(size_t)(n0 + n) * DIN + d]) * 1.4426950408889634f;
    const float Dd = Dp[d];

    float h[4] = {0.f, 0.f, 0.f, 0.f};
    const float* dbcb = g_dbc + (size_t)b * LEN * DBCW + DTRANK;
    const size_t base = (size_t)b * LEN;

    // prefetch l = 0
    size_t r0 = base * DIN + d;
    float dlt = g_delta[r0];
    float xv  = g_xc[r0];
    float zv  = g_xz[base * (2 * DIN) + DIN + d];

    for (int l = 0; l < LEN; l++) {
        float c_dlt = dlt, c_x = xv, c_z = zv;
        int ln = (l + 1 < LEN) ? l + 1 : l;            // prefetch next
        size_t rn = (base + ln) * DIN + d;
        dlt = g_delta[rn];
        xv  = g_xc[rn];
        zv  = g_xz[(base + ln) * (2 * DIN) + DIN + d];

        const float* bc = dbcb + (size_t)l * DBCW;
        float dx = c_dlt * c_x;
        float yv = 0.f;
#pragma unroll
        for (int n = 0; n < 4; n++) {
            float Bn = bc[n0 + n];
            float Cn = bc[DSTATE + n0 + n];
            float dA = exp2f(c_dlt * A2[n]);
            h[n] = fmaf(dA, h[n], Bn * dx);
            yv = fmaf(Cn, h[n], yv);
        }
        yv += __shfl_xor_sync(0xFFFFFFFFu, yv, 1);
        yv += __shfl_xor_sync(0xFFFFFFFFu, yv, 2);
        if (q == 0) {
            float y = fmaf(Dd, c_x, yv);
            float gate = c_z / (1.f + __expf(-c_z));
            float o = y * gate;
            size_t oi = (base + l) * DIN + d;
            __nv_bfloat16 hi = __float2bfloat16(o);
            g_yh[oi] = hi;
            g_yl[oi] = __float2bfloat16(o - __bfloat162float(hi));
        }
    }
}

// ---------------- launch ---------------------------------------------------
extern "C" void kernel_launch(void* const* d_in, const int* in_sizes, int n_in,
                              void* d_out, int out_size)
{
    const float* x      = (const float*)d_in[0];
    const float* W_in   = (const float*)d_in[1];
    const float* conv_w = (const float*)d_in[2];
    const float* conv_b = (const float*)d_in[3];
    const float* W_x    = (const float*)d_in[4];
    const float* W_dt   = (const float*)d_in[5];
    const float* b_dt   = (const float*)d_in[6];
    const float* A_raw  = (const float*)d_in[7];
    const float* Dp     = (const float*)d_in[8];
    const float* W_out  = (const float*)d_in[9];
    float* out = (float*)d_out;

    float *p_xz, *p_dbc, *p_delta;
    __nv_bfloat16 *p_xh, *p_xl, *p_Winh, *p_Winl, *p_xch, *p_xcl, *p_Wxh, *p_Wxl;
    __nv_bfloat16 *p_dth, *p_dtl, *p_Wdth, *p_Wdtl, *p_yh, *p_yl, *p_Wouth, *p_Woutl;
    cudaGetSymbolAddress((void**)&p_xz,    g_xz);
    cudaGetSymbolAddress((void**)&p_dbc,   g_dbc);
    cudaGetSymbolAddress((void**)&p_delta, g_delta);
    cudaGetSymbolAddress((void**)&p_xh,    g_xh);
    cudaGetSymbolAddress((void**)&p_xl,    g_xl);
    cudaGetSymbolAddress((void**)&p_Winh,  g_Winh);
    cudaGetSymbolAddress((void**)&p_Winl,  g_Winl);
    cudaGetSymbolAddress((void**)&p_xch,   g_xch);
    cudaGetSymbolAddress((void**)&p_xcl,   g_xcl);
    cudaGetSymbolAddress((void**)&p_Wxh,   g_Wxh);
    cudaGetSymbolAddress((void**)&p_Wxl,   g_Wxl);
    cudaGetSymbolAddress((void**)&p_dth,   g_dth);
    cudaGetSymbolAddress((void**)&p_dtl,   g_dtl);
    cudaGetSymbolAddress((void**)&p_Wdth,  g_Wdth);
    cudaGetSymbolAddress((void**)&p_Wdtl,  g_Wdtl);
    cudaGetSymbolAddress((void**)&p_yh,    g_yh);
    cudaGetSymbolAddress((void**)&p_yl,    g_yl);
    cudaGetSymbolAddress((void**)&p_Wouth, g_Wouth);
    cudaGetSymbolAddress((void**)&p_Woutl, g_Woutl);

    const int GSMEM = 1024 + 3 * 32768;   // align slack + 3 stages x (A16K+B16K)
    cudaFuncSetAttribute(gemm_hl<0>, cudaFuncAttributeMaxDynamicSharedMemorySize, GSMEM);
    cudaFuncSetAttribute(gemm_hl<1>, cudaFuncAttributeMaxDynamicSharedMemorySize, GSMEM);
    cudaFuncSetAttribute(gemm_hl<2>, cudaFuncAttributeMaxDynamicSharedMemorySize, GSMEM);

    // 1. splits for in-proj
    split_hl<<<(ML * DMODEL / 4 + 255) / 256, 256>>>(x, p_xh, p_xl, ML * DMODEL / 4);
    split_hl<<<(2 * DIN * DMODEL / 4 + 255) / 256, 256>>>(W_in, p_Winh, p_Winl,
                                                          2 * DIN * DMODEL / 4);
    // 2. in-proj GEMM: (8192 x 4096) K=1024
    gemm_hl<0><<<dim3(4096 / 128, ML / 128), 256, GSMEM>>>(
        p_xh, p_xl, p_Winh, p_Winl, p_xz, 4096, DMODEL, nullptr);
    // 3. conv + SiLU (+ bf16 split of xc)
    conv_silu_kernel<<<(ML * DIN + 255) / 256, 256>>>(conv_w, conv_b);
    // 4. x-proj GEMM: (8192 x 96) K=2048, fused dt hi/lo split in epilogue
    split_hl<<<(DBCW * DIN / 4 + 255) / 256, 256>>>(W_x, p_Wxh, p_Wxl, DBCW * DIN / 4);
    gemm_hl<2><<<dim3(1, ML / 128), 256, GSMEM>>>(
        p_xch, p_xcl, p_Wxh, p_Wxl, p_dbc, DBCW, DIN, nullptr);
    // 5. delta GEMM with fused bias+softplus: (8192 x 2048) K=64
    split_hl<<<(DIN * DTRANK / 4 + 255) / 256, 256>>>(W_dt, p_Wdth, p_Wdtl,
                                                      DIN * DTRANK / 4);
    gemm_hl<1><<<dim3(DIN / 128, ML / 128), 256, GSMEM>>>(
        p_dth, p_dtl, p_Wdth, p_Wdtl, p_delta, DIN, DTRANK, b_dt);
    // 6. selective scan (+D skip, gate, bf16 split of y)
    scan_kernel<<<dim3(DIN / 64, BATCH), 256>>>(A_raw, Dp);
    // 7. out-proj GEMM: (8192 x 1024) K=2048
    split_hl<<<(DMODEL * DIN / 4 + 255) / 256, 256>>>(W_out, p_Wouth, p_Woutl,
                                                      DMODEL * DIN / 4);
    gemm_hl<0><<<dim3(DMODEL / 128, ML / 128), 256, GSMEM>>>(
        p_yh, p_yl, p_Wouth, p_Woutl, out, DMODEL, DIN, nullptr);
}

// round 9
// speedup vs baseline: 1.0976x; 1.0855x over previous
#include <cuda_runtime.h>
#include <cuda_bf16.h>
#include <math.h>
#include <stdint.h>

#define BATCH  4
#define LEN    2048
#define DMODEL 1024
#define DIN    2048
#define DSTATE 16
#define DTRANK 64
#define DCONV  4
#define ML     (BATCH * LEN)          // 8192 rows
#define RH     (ML / 2)               // 4096 rows per half
#define DBCW   (DTRANK + 2 * DSTATE)  // 96

// ---------------- fp32 scratch ----------------
__device__ float g_xz[(size_t)ML * 2 * DIN];   // in-proj output (xc | z)
__device__ float g_xc[(size_t)ML * DIN];       // conv+silu output (fp32 for scan)
__device__ float g_dbc[(size_t)ML * DBCW];     // dt | B | C
__device__ float g_delta[(size_t)ML * DIN];    // softplus(dt @ W_dt + b)

// ---------------- bf16 hi/lo scratch ----------------
__device__ __align__(16) __nv_bfloat16 g_xh[(size_t)ML * DMODEL];
__device__ __align__(16) __nv_bfloat16 g_xl[(size_t)ML * DMODEL];
__device__ __align__(16) __nv_bfloat16 g_Winh[(size_t)2 * DIN * DMODEL];
__device__ __align__(16) __nv_bfloat16 g_Winl[(size_t)2 * DIN * DMODEL];
__device__ __align__(16) __nv_bfloat16 g_xch[(size_t)ML * DIN];
__device__ __align__(16) __nv_bfloat16 g_xcl[(size_t)ML * DIN];
__device__ __align__(16) __nv_bfloat16 g_Wxh[(size_t)DBCW * DIN];
__device__ __align__(16) __nv_bfloat16 g_Wxl[(size_t)DBCW * DIN];
__device__ __align__(16) __nv_bfloat16 g_dth[(size_t)ML * DTRANK];
__device__ __align__(16) __nv_bfloat16 g_dtl[(size_t)ML * DTRANK];
__device__ __align__(16) __nv_bfloat16 g_Wdth[(size_t)DIN * DTRANK];
__device__ __align__(16) __nv_bfloat16 g_Wdtl[(size_t)DIN * DTRANK];
__device__ __align__(16) __nv_bfloat16 g_yh[(size_t)ML * DIN];
__device__ __align__(16) __nv_bfloat16 g_yl[(size_t)ML * DIN];
__device__ __align__(16) __nv_bfloat16 g_Wouth[(size_t)DMODEL * DIN];
__device__ __align__(16) __nv_bfloat16 g_Woutl[(size_t)DMODEL * DIN];

// ---------------- PTX helpers (base sm_103-legal only) ----------------
__device__ __forceinline__ uint32_t s2u(const void* p) {
    uint32_t a;
    asm("{ .reg .u64 t; cvta.to.shared.u64 t, %1; cvt.u32.u64 %0, t; }" : "=r"(a) : "l"(p));
    return a;
}
__device__ __forceinline__ void cpasync16(uint32_t dst, const void* src, int sz) {
    asm volatile("cp.async.cg.shared.global [%0], [%1], 16, %2;"
                 :: "r"(dst), "l"(src), "r"(sz) : "memory");
}
__device__ __forceinline__ void ldsm4(uint32_t* r, uint32_t addr) {
    asm volatile("ldmatrix.sync.aligned.m8n8.x4.shared.b16 {%0,%1,%2,%3}, [%4];"
                 : "=r"(r[0]), "=r"(r[1]), "=r"(r[2]), "=r"(r[3]) : "r"(addr));
}
__device__ __forceinline__ void mma16816(float* d, const uint32_t* a,
                                         uint32_t b0, uint32_t b1) {
    asm volatile(
        "mma.sync.aligned.m16n8k16.row.col.f32.bf16.bf16.f32 "
        "{%0,%1,%2,%3}, {%4,%5,%6,%7}, {%8,%9}, {%0,%1,%2,%3};"
        : "+f"(d[0]), "+f"(d[1]), "+f"(d[2]), "+f"(d[3])
        : "r"(a[0]), "r"(a[1]), "r"(a[2]), "r"(a[3]), "r"(b0), "r"(b1));
}
#define SWZ(o) ((o) ^ (((o) >> 3) & 0x70))

// ============================================================================
// split-bf16 GEMM (mma.sync):  C[m,n] = sum_k A[m,k]*B[n,k]
//   3 K-segments: Ah*Bh + Al*Bh + Ah*Bl.  CTA tile 128x128, BK=64,
//   2-stage cp.async double buffer (best-measured schedule), SW128 swizzle,
//   8 warps at 64x32 warp tiles.
//   M (via grid) % 128 == 0, K % 64 == 0; B rows >= N zero-filled.
//   EPI: 0 = plain store
//        1 = softplus(acc + bias[n])
//        2 = plain store + (n < DTRANK) fused bf16 hi/lo split into dth/dtl
// ============================================================================
template <int EPI>
__global__ __launch_bounds__(256) void gemm_hl(
    const __nv_bfloat16* __restrict__ Ah, const __nv_bfloat16* __restrict__ Al,
    const __nv_bfloat16* __restrict__ Bh, const __nv_bfloat16* __restrict__ Bl,
    float* __restrict__ C, int N, int K, const float* __restrict__ bias,
    __nv_bfloat16* __restrict__ dth, __nv_bfloat16* __restrict__ dtl)
{
    extern __shared__ char dsm[];
    char* base = (char*)((((uintptr_t)dsm) + 1023) & ~(uintptr_t)1023);
    const uint32_t sA[2] = { s2u(base),         s2u(base) + 16384 };
    const uint32_t sB[2] = { s2u(base) + 32768, s2u(base) + 49152 };

    const int tid = threadIdx.x, lane = tid & 31, wid = tid >> 5;
    const int wm = (wid >> 2) * 64, wn = (wid & 3) * 32;
    const int m0 = blockIdx.y * 128, n0 = blockIdx.x * 128;
    const int kcs = K >> 6, T = 3 * kcs;

    float acc[4][4][4];
#pragma unroll
    for (int i = 0; i < 4; i++)
#pragma unroll
        for (int j = 0; j < 4; j++)
#pragma unroll
            for (int r = 0; r < 4; r++) acc[i][j][r] = 0.f;

    auto loadChunk = [&](int c, int buf) {
        const int seg = c / kcs, kc = c - seg * kcs, koff = kc * 64;
        const __nv_bfloat16* Ap = (seg == 1) ? Al : Ah;
        const __nv_bfloat16* Bp = (seg == 2) ? Bl : Bh;
#pragma unroll
        for (int q = 0; q < 4; q++) {                  // A: 128 x 64
            int idx = tid + q * 256, r = idx >> 3, c8 = idx & 7;
            uint32_t o = (uint32_t)(r * 128 + c8 * 16);
            cpasync16(sA[buf] + SWZ(o), Ap + (size_t)(m0 + r) * K + koff + c8 * 8, 16);
        }
#pragma unroll
        for (int q = 0; q < 4; q++) {                  // B: 128 x 64 (zfill rows >= N)
            int idx = tid + q * 256, r = idx >> 3, c8 = idx & 7;
            int nr = n0 + r;
            int ok = (nr < N) ? 16 : 0;
            uint32_t o = (uint32_t)(r * 128 + c8 * 16);
            cpasync16(sB[buf] + SWZ(o),
                      Bp + (size_t)((nr < N) ? nr : 0) * K + koff + c8 * 8, ok);
        }
        asm volatile("cp.async.commit_group;" ::: "memory");
    };

    loadChunk(0, 0);
    for (int c = 0; c < T; c++) {
        const int buf = c & 1;
        if (c + 1 < T) {
            loadChunk(c + 1, buf ^ 1);
            asm volatile("cp.async.wait_group 1;" ::: "memory");
        } else {
            asm volatile("cp.async.wait_group 0;" ::: "memory");
        }
        __syncthreads();

        const int rsel = lane & 15;
#pragma unroll
        for (int kb = 0; kb < 64; kb += 16) {
            const int kk = kb + ((lane & 16) >> 1);
            uint32_t af[4][4], bfr[2][4];
#pragma unroll
            for (int mi = 0; mi < 4; mi++) {
                uint32_t o = (uint32_t)((wm + mi * 16 + rsel) * 128 + kk * 2);
                ldsm4(af[mi], sA[buf] + SWZ(o));
            }
#pragma unroll
            for (int nb = 0; nb < 2; nb++) {
                uint32_t o = (uint32_t)((wn + nb * 16 + rsel) * 128 + kk * 2);
                ldsm4(bfr[nb], sB[buf] + SWZ(o));
            }
#pragma unroll
            for (int mi = 0; mi < 4; mi++)
#pragma unroll
                for (int nj = 0; nj < 4; nj++)
                    mma16816(acc[mi][nj], af[mi],
                             bfr[nj >> 1][nj & 1], bfr[nj >> 1][(nj & 1) + 2]);
        }
        __syncthreads();
    }

    // epilogue
#pragma unroll
    for (int mi = 0; mi < 4; mi++)
#pragma unroll
        for (int h = 0; h < 2; h++) {
            int m = m0 + wm + mi * 16 + (lane >> 2) + h * 8;
#pragma unroll
            for (int nj = 0; nj < 4; nj++) {
                int n = n0 + wn + nj * 8 + (lane & 3) * 2;
                if (n < N) {
                    float v0 = acc[mi][nj][h * 2 + 0];
                    float v1 = acc[mi][nj][h * 2 + 1];
                    if (EPI == 1) {
                        v0 += bias[n];
                        v1 += bias[n + 1];
                        v0 = fmaxf(v0, 0.f) + log1pf(expf(-fabsf(v0)));
                        v1 = fmaxf(v1, 0.f) + log1pf(expf(-fabsf(v1)));
                    }
                    *(float2*)(C + (size_t)m * N + n) = make_float2(v0, v1);
                    if (EPI == 2 && n < DTRANK) {      // fused dt hi/lo split
                        __nv_bfloat16 h0 = __float2bfloat16(v0);
                        __nv_bfloat16 h1 = __float2bfloat16(v1);
                        __nv_bfloat16 l0 = __float2bfloat16(v0 - __bfloat162float(h0));
                        __nv_bfloat16 l1 = __float2bfloat16(v1 - __bfloat162float(h1));
                        size_t o = (size_t)m * DTRANK + n;
                        *(__nv_bfloat162*)(dth + o) = __nv_bfloat162(h0, h1);
                        *(__nv_bfloat162*)(dtl + o) = __nv_bfloat162(l0, l1);
                    }
                }
            }
        }
}

// ---------------- fp32 -> (hi, lo) bf16 split, contiguous ----------------
__global__ __launch_bounds__(256) void split_hl(
    const float* __restrict__ src, __nv_bfloat16* __restrict__ h,
    __nv_bfloat16* __restrict__ l, int n4)
{
    int i = blockIdx.x * 256 + threadIdx.x;
    if (i >= n4) return;
    float4 v = ((const float4*)src)[i];
    __nv_bfloat16 h0 = __float2bfloat16(v.x), h1 = __float2bfloat16(v.y);
    __nv_bfloat16 h2 = __float2bfloat16(v.z), h3 = __float2bfloat16(v.w);
    __nv_bfloat16 l0 = __float2bfloat16(v.x - __bfloat162float(h0));
    __nv_bfloat16 l1 = __float2bfloat16(v.y - __bfloat162float(h1));
    __nv_bfloat16 l2 = __float2bfloat16(v.z - __bfloat162float(h2));
    __nv_bfloat16 l3 = __float2bfloat16(v.w - __bfloat162float(h3));
    ((__nv_bfloat162*)h)[i * 2 + 0] = __nv_bfloat162(h0, h1);
    ((__nv_bfloat162*)h)[i * 2 + 1] = __nv_bfloat162(h2, h3);
    ((__nv_bfloat162*)l)[i * 2 + 0] = __nv_bfloat162(l0, l1);
    ((__nv_bfloat162*)l)[i * 2 + 1] = __nv_bfloat162(l2, l3);
}

// ---------------- causal depthwise conv (k=4) + bias + SiLU + bf16 split ----
// Processes 2 batches starting at b0; grid covers RH*DIN elements.
__global__ __launch_bounds__(256) void conv_silu_kernel(
    const float* __restrict__ w, const float* __restrict__ bias, int b0)
{
    int idx = blockIdx.x * blockDim.x + threadIdx.x;
    if (idx >= RH * DIN) return;
    int d = idx & (DIN - 1);
    int l = (idx >> 11) & (LEN - 1);
    int b = b0 + (idx >> 22);

    float acc = bias[d];
    const float* wd = w + d * DCONV;
#pragma unroll
    for (int j = 0; j < DCONV; j++) {
        int ll = l - (DCONV - 1) + j;
        if (ll >= 0)
            acc = fmaf(wd[j], g_xz[((size_t)(b * LEN + ll)) * (2 * DIN) + d], acc);
    }
    float s = acc / (1.f + __expf(-acc));
    size_t gidx = ((size_t)(b * LEN + l)) * DIN + d;
    g_xc[gidx] = s;
    __nv_bfloat16 hi = __float2bfloat16(s);
    g_xch[gidx] = hi;
    g_xcl[gidx] = __float2bfloat16(s - __bfloat162float(hi));
}

// ---------------- selective scan + D skip + SiLU(z) gate + bf16 split ------
// grid (DIN/64, 2), 256 threads: 64 channels x 4 state-quads; batches b0+blockIdx.y
__global__ __launch_bounds__(256) void scan_kernel(
    const float* __restrict__ A_raw, const float* __restrict__ Dp, int b0)
{
    const int b = b0 + blockIdx.y;
    const int d = blockIdx.x * 64 + (threadIdx.x >> 2);
    const int q = threadIdx.x & 3;
    const int n0 = q * 4;

    float A2[4];
#pragma unroll
    for (int n = 0; n < 4; n++)
        A2[n] = -expf(A_raw[(size_t)(n0 + n) * DIN + d]) * 1.4426950408889634f;
    const float Dd = Dp[d];

    float h[4] = {0.f, 0.f, 0.f, 0.f};
    const float* dbcb = g_dbc + (size_t)b * LEN * DBCW + DTRANK;
    const size_t base = (size_t)b * LEN;

    // prefetch l = 0
    size_t r0 = base * DIN + d;
    float dlt = g_delta[r0];
    float xv  = g_xc[r0];
    float zv  = g_xz[base * (2 * DIN) + DIN + d];

    for (int l = 0; l < LEN; l++) {
        float c_dlt = dlt, c_x = xv, c_z = zv;
        int ln = (l + 1 < LEN) ? l + 1 : l;            // prefetch next
        size_t rn = (base + ln) * DIN + d;
        dlt = g_delta[rn];
        xv  = g_xc[rn];
        zv  = g_xz[(base + ln) * (2 * DIN) + DIN + d];

        const float* bc = dbcb + (size_t)l * DBCW;
        float dx = c_dlt * c_x;
        float yv = 0.f;
#pragma unroll
        for (int n = 0; n < 4; n++) {
            float Bn = bc[n0 + n];
            float Cn = bc[DSTATE + n0 + n];
            float dA = exp2f(c_dlt * A2[n]);
            h[n] = fmaf(dA, h[n], Bn * dx);
            yv = fmaf(Cn, h[n], yv);
        }
        yv += __shfl_xor_sync(0xFFFFFFFFu, yv, 1);
        yv += __shfl_xor_sync(0xFFFFFFFFu, yv, 2);
        if (q == 0) {
            float y = fmaf(Dd, c_x, yv);
            float gate = c_z / (1.f + __expf(-c_z));
            float o = y * gate;
            size_t oi = (base + l) * DIN + d;
            __nv_bfloat16 hi = __float2bfloat16(o);
            g_yh[oi] = hi;
            g_yl[oi] = __float2bfloat16(o - __bfloat162float(hi));
        }
    }
}

// ---------------- launch: 2 batch-half chains on 2 streams -----------------
extern "C" void kernel_launch(void* const* d_in, const int* in_sizes, int n_in,
                              void* d_out, int out_size)
{
    const float* x      = (const float*)d_in[0];
    const float* W_in   = (const float*)d_in[1];
    const float* conv_w = (const float*)d_in[2];
    const float* conv_b = (const float*)d_in[3];
    const float* W_x    = (const float*)d_in[4];
    const float* W_dt   = (const float*)d_in[5];
    const float* b_dt   = (const float*)d_in[6];
    const float* A_raw  = (const float*)d_in[7];
    const float* Dp     = (const float*)d_in[8];
    const float* W_out  = (const float*)d_in[9];
    float* out = (float*)d_out;

    float *p_xz, *p_dbc, *p_delta;
    __nv_bfloat16 *p_xh, *p_xl, *p_Winh, *p_Winl, *p_xch, *p_xcl, *p_Wxh, *p_Wxl;
    __nv_bfloat16 *p_dth, *p_dtl, *p_Wdth, *p_Wdtl, *p_yh, *p_yl, *p_Wouth, *p_Woutl;
    cudaGetSymbolAddress((void**)&p_xz,    g_xz);
    cudaGetSymbolAddress((void**)&p_dbc,   g_dbc);
    cudaGetSymbolAddress((void**)&p_delta, g_delta);
    cudaGetSymbolAddress((void**)&p_xh,    g_xh);
    cudaGetSymbolAddress((void**)&p_xl,    g_xl);
    cudaGetSymbolAddress((void**)&p_Winh,  g_Winh);
    cudaGetSymbolAddress((void**)&p_Winl,  g_Winl);
    cudaGetSymbolAddress((void**)&p_xch,   g_xch);
    cudaGetSymbolAddress((void**)&p_xcl,   g_xcl);
    cudaGetSymbolAddress((void**)&p_Wxh,   g_Wxh);
    cudaGetSymbolAddress((void**)&p_Wxl,   g_Wxl);
    cudaGetSymbolAddress((void**)&p_dth,   g_dth);
    cudaGetSymbolAddress((void**)&p_dtl,   g_dtl);
    cudaGetSymbolAddress((void**)&p_Wdth,  g_Wdth);
    cudaGetSymbolAddress((void**)&p_Wdtl,  g_Wdtl);
    cudaGetSymbolAddress((void**)&p_yh,    g_yh);
    cudaGetSymbolAddress((void**)&p_yl,    g_yl);
    cudaGetSymbolAddress((void**)&p_Wouth, g_Wouth);
    cudaGetSymbolAddress((void**)&p_Woutl, g_Woutl);

    const int GSMEM = 1024 + 4 * 16384;   // align slack + 2 stages x (A16K+B16K)
    static bool s_init = false;
    static cudaStream_t st0, st1, stw;
    static cudaEvent_t evS, evWin, evWx, evWdt, evWout, evD0, evD1;
    if (!s_init) {
        cudaFuncSetAttribute(gemm_hl<0>, cudaFuncAttributeMaxDynamicSharedMemorySize, GSMEM);
        cudaFuncSetAttribute(gemm_hl<1>, cudaFuncAttributeMaxDynamicSharedMemorySize, GSMEM);
        cudaFuncSetAttribute(gemm_hl<2>, cudaFuncAttributeMaxDynamicSharedMemorySize, GSMEM);
        cudaStreamCreateWithFlags(&st0, cudaStreamNonBlocking);
        cudaStreamCreateWithFlags(&st1, cudaStreamNonBlocking);
        cudaStreamCreateWithFlags(&stw, cudaStreamNonBlocking);
        cudaEventCreateWithFlags(&evS,    cudaEventDisableTiming);
        cudaEventCreateWithFlags(&evWin,  cudaEventDisableTiming);
        cudaEventCreateWithFlags(&evWx,   cudaEventDisableTiming);
        cudaEventCreateWithFlags(&evWdt,  cudaEventDisableTiming);
        cudaEventCreateWithFlags(&evWout, cudaEventDisableTiming);
        cudaEventCreateWithFlags(&evD0,   cudaEventDisableTiming);
        cudaEventCreateWithFlags(&evD1,   cudaEventDisableTiming);
        s_init = true;
    }

    // fork from the origin (capture) stream
    cudaEventRecord(evS, 0);
    cudaStreamWaitEvent(st0, evS, 0);
    cudaStreamWaitEvent(st1, evS, 0);
    cudaStreamWaitEvent(stw, evS, 0);

    // weight splits on stw
    split_hl<<<(2 * DIN * DMODEL / 4 + 255) / 256, 256, 0, stw>>>(
        W_in, p_Winh, p_Winl, 2 * DIN * DMODEL / 4);
    cudaEventRecord(evWin, stw);
    split_hl<<<(DBCW * DIN / 4 + 255) / 256, 256, 0, stw>>>(
        W_x, p_Wxh, p_Wxl, DBCW * DIN / 4);
    cudaEventRecord(evWx, stw);
    split_hl<<<(DIN * DTRANK / 4 + 255) / 256, 256, 0, stw>>>(
        W_dt, p_Wdth, p_Wdtl, DIN * DTRANK / 4);
    cudaEventRecord(evWdt, stw);
    split_hl<<<(DMODEL * DIN / 4 + 255) / 256, 256, 0, stw>>>(
        W_out, p_Wouth, p_Woutl, DMODEL * DIN / 4);
    cudaEventRecord(evWout, stw);

    // two batch-half chains
    for (int h = 0; h < 2; h++) {
        cudaStream_t s = h ? st1 : st0;
        const size_t r0 = (size_t)h * RH;

        // split x half
        split_hl<<<(RH * DMODEL / 4 + 255) / 256, 256, 0, s>>>(
            x + r0 * DMODEL, p_xh + r0 * DMODEL, p_xl + r0 * DMODEL, RH * DMODEL / 4);
        // in-proj GEMM: (4096 x 4096) K=1024
        cudaStreamWaitEvent(s, evWin, 0);
        gemm_hl<0><<<dim3(32, RH / 128), 256, GSMEM, s>>>(
            p_xh + r0 * DMODEL, p_xl + r0 * DMODEL, p_Winh, p_Winl,
            p_xz + r0 * 2 * DIN, 4096, DMODEL, nullptr, nullptr, nullptr);
        // conv + SiLU + xc split
        conv_silu_kernel<<<(RH * DIN + 255) / 256, 256, 0, s>>>(conv_w, conv_b, 2 * h);
        // x-proj GEMM (4096 x 96) K=2048, fused dt split
        cudaStreamWaitEvent(s, evWx, 0);
        gemm_hl<2><<<dim3(1, RH / 128), 256, GSMEM, s>>>(
            p_xch + r0 * DIN, p_xcl + r0 * DIN, p_Wxh, p_Wxl,
            p_dbc + r0 * DBCW, DBCW, DIN, nullptr,
            p_dth + r0 * DTRANK, p_dtl + r0 * DTRANK);
        // delta GEMM (4096 x 2048) K=64, fused bias+softplus
        cudaStreamWaitEvent(s, evWdt, 0);
        gemm_hl<1><<<dim3(16, RH / 128), 256, GSMEM, s>>>(
            p_dth + r0 * DTRANK, p_dtl + r0 * DTRANK, p_Wdth, p_Wdtl,
            p_delta + r0 * DIN, DIN, DTRANK, b_dt, nullptr, nullptr);
        // selective scan (2 batches)
        scan_kernel<<<dim3(DIN / 64, 2), 256, 0, s>>>(A_raw, Dp, 2 * h);
        // out-proj GEMM (4096 x 1024) K=2048
        cudaStreamWaitEvent(s, evWout, 0);
        gemm_hl<0><<<dim3(8, RH / 128), 256, GSMEM, s>>>(
            p_yh + r0 * DIN, p_yl + r0 * DIN, p_Wouth, p_Woutl,
            out + r0 * DMODEL, DMODEL, DIN, nullptr, nullptr, nullptr);
        cudaEventRecord(h ? evD1 : evD0, s);
    }

    // join back onto the origin stream
    cudaStreamWaitEvent(0, evD0, 0);
    cudaStreamWaitEvent(0, evD1, 0);
}